// round 1
// baseline (speedup 1.0000x reference)
#include <cuda_runtime.h>
#include <cstdint>

#define BATCH 4
#define L 4096
#define CM 192
#define DI 384
#define DS 16
#define DTR 12
#define M_ROWS (BATCH * L)   // 16384
#define NCH 32
#define CHL (L / NCH)        // 128

// ---------------- scratch (device globals; no allocation) ----------------
__device__ float g_xi[(size_t)M_ROWS * DI];       // conv input, (m, d) layout
__device__ float g_z[(size_t)M_ROWS * DI];        // gate branch
__device__ float g_u[(size_t)M_ROWS * DI];        // conv+silu output
__device__ float g_delta[(size_t)M_ROWS * DI];
__device__ float g_Bs[(size_t)M_ROWS * DS];
__device__ float g_Cs[(size_t)M_ROWS * DS];
__device__ float g_y[(size_t)M_ROWS * DI];
__device__ float g_hpart[(size_t)BATCH * DI * DS * NCH];
__device__ float g_aP[(size_t)BATCH * DI * DS * NCH];
__device__ float g_hin[(size_t)BATCH * DI * DS * NCH];

// ---------------- K1: xz = x @ W_in  (16384 x 768, K=192) ----------------
// 64x64 tile, BK=16, 256 threads, 4x4 per thread.
__global__ void k_gemm_in(const float* __restrict__ X, const float* __restrict__ Win)
{
    __shared__ float As[16][64];
    __shared__ float Bs[16][64];
    const int tid = threadIdx.x;
    const int m0 = blockIdx.x * 64;
    const int n0 = blockIdx.y * 64;
    const int tm = tid / 16, tn = tid % 16;

    const int arow = tid / 4;
    const int acol4 = (tid % 4) * 4;
    const int brow = tid / 16;
    const int bcol4 = (tid % 16) * 4;

    float acc[4][4];
#pragma unroll
    for (int i = 0; i < 4; i++)
#pragma unroll
        for (int j = 0; j < 4; j++) acc[i][j] = 0.f;

    for (int k0 = 0; k0 < CM; k0 += 16) {
        float4 av = *(const float4*)&X[(size_t)(m0 + arow) * CM + k0 + acol4];
        As[acol4 + 0][arow] = av.x;
        As[acol4 + 1][arow] = av.y;
        As[acol4 + 2][arow] = av.z;
        As[acol4 + 3][arow] = av.w;
        float4 bv = *(const float4*)&Win[(size_t)(k0 + brow) * (2 * DI) + n0 + bcol4];
        *(float4*)&Bs[brow][bcol4] = bv;
        __syncthreads();
#pragma unroll
        for (int k = 0; k < 16; k++) {
            float4 a4 = *(const float4*)&As[k][tm * 4];
            float4 b4 = *(const float4*)&Bs[k][tn * 4];
            float a[4] = {a4.x, a4.y, a4.z, a4.w};
            float b[4] = {b4.x, b4.y, b4.z, b4.w};
#pragma unroll
            for (int i = 0; i < 4; i++)
#pragma unroll
                for (int j = 0; j < 4; j++) acc[i][j] = fmaf(a[i], b[j], acc[i][j]);
        }
        __syncthreads();
    }
#pragma unroll
    for (int i = 0; i < 4; i++) {
        const int m = m0 + tm * 4 + i;
#pragma unroll
        for (int j = 0; j < 4; j++) {
            const int n = n0 + tn * 4 + j;
            const float v = acc[i][j];
            if (n < DI) g_xi[(size_t)m * DI + n] = v;
            else        g_z[(size_t)m * DI + (n - DI)] = v;
        }
    }
}

// ---------------- conv: depthwise 3x3 + bias + SiLU (channel-last) ----------------
// block (128 d-lanes, 4 pixels); grid (1024 px-groups, 3 d-tiles, 4 batches)
__global__ void k_conv(const float* __restrict__ cw, const float* __restrict__ cb)
{
    const int b = blockIdx.z;
    const int d = blockIdx.y * 128 + threadIdx.x;
    const int px = blockIdx.x * 4 + threadIdx.y;
    const int h = px >> 6;
    const int w = px & 63;

    const float* w9 = cw + d * 9;
    float acc = cb[d];
    const size_t base = (size_t)b * L * DI;
#pragma unroll
    for (int dh = -1; dh <= 1; dh++) {
        const int hh = h + dh;
        if (hh < 0 || hh > 63) continue;
#pragma unroll
        for (int dw = -1; dw <= 1; dw++) {
            const int ww = w + dw;
            if (ww < 0 || ww > 63) continue;
            acc = fmaf(g_xi[base + (size_t)(hh * 64 + ww) * DI + d],
                       w9[(dh + 1) * 3 + (dw + 1)], acc);
        }
    }
    const float sig = 1.f / (1.f + __expf(-acc));
    g_u[base + (size_t)px * DI + d] = acc * sig;
}

// ---------------- K2: per-row x_dbl / delta / Bs / Cs ----------------
__global__ void k_proj(const float* __restrict__ prompt, const float* __restrict__ Wx,
                       const float* __restrict__ Wdt, const float* __restrict__ bdt,
                       const float* __restrict__ Wp)
{
    __shared__ float ur[DI];
    __shared__ float sd[44];
    __shared__ float pc[DS];
    const int row = blockIdx.x;
    const int tx = threadIdx.x; // 128

    const float* urow = g_u + (size_t)row * DI;
    ur[tx] = urow[tx];
    ur[tx + 128] = urow[tx + 128];
    ur[tx + 256] = urow[tx + 256];
    __syncthreads();

    if (tx < 44) {
        float a0 = 0.f, a1 = 0.f;
#pragma unroll 8
        for (int k = 0; k < DI; k += 2) {
            a0 = fmaf(ur[k],     Wx[(size_t)k * 44 + tx],       a0);
            a1 = fmaf(ur[k + 1], Wx[(size_t)(k + 1) * 44 + tx], a1);
        }
        sd[tx] = a0 + a1;
    } else if (tx >= 64 && tx < 64 + DS) {
        const int n = tx - 64;
        const float* pr = prompt + (size_t)row * CM;
        float a0 = 0.f, a1 = 0.f;
#pragma unroll 8
        for (int k = 0; k < CM; k += 2) {
            a0 = fmaf(pr[k],     Wp[(size_t)k * DS + n],       a0);
            a1 = fmaf(pr[k + 1], Wp[(size_t)(k + 1) * DS + n], a1);
        }
        pc[n] = a0 + a1;
    }
    __syncthreads();

    if (tx < DS) {
        g_Bs[(size_t)row * DS + tx] = sd[DTR + tx];
        g_Cs[(size_t)row * DS + tx] = sd[DTR + DS + tx] + pc[tx];
    }
#pragma unroll
    for (int j = 0; j < 3; j++) {
        const int d = tx + 128 * j;
        float acc = bdt[d];
#pragma unroll
        for (int r = 0; r < DTR; r++) acc = fmaf(sd[r], Wdt[(size_t)r * DI + d], acc);
        const float sp = acc > 20.f ? acc : log1pf(__expf(acc));
        g_delta[(size_t)row * DI + d] = sp;
    }
}

// ---------------- S1: per-chunk partial scan (h0 = 0) ----------------
__global__ void k_scan1(const float* __restrict__ Alog)
{
    const int d = blockIdx.x * 128 + threadIdx.x;
    const int c = blockIdx.y;
    const int b = blockIdx.z;

    float A[DS];
#pragma unroll
    for (int n = 0; n < DS; n++) A[n] = -__expf(Alog[d * DS + n]);

    float h[DS];
#pragma unroll
    for (int n = 0; n < DS; n++) h[n] = 0.f;
    float dsum = 0.f;

    const int l0 = c * CHL;
    const float* dp = g_delta + ((size_t)b * L + l0) * DI + d;
    const float* up = g_u + ((size_t)b * L + l0) * DI + d;
    const float4* bp = reinterpret_cast<const float4*>(g_Bs) + ((size_t)b * L + l0) * 4;

    for (int l = 0; l < CHL; l++) {
        const float dl = dp[(size_t)l * DI];
        const float uu = up[(size_t)l * DI];
        const float du = dl * uu;
        dsum += dl;
        const float4 q0 = bp[l * 4 + 0], q1 = bp[l * 4 + 1],
                     q2 = bp[l * 4 + 2], q3 = bp[l * 4 + 3];
        const float bv[DS] = {q0.x, q0.y, q0.z, q0.w, q1.x, q1.y, q1.z, q1.w,
                              q2.x, q2.y, q2.z, q2.w, q3.x, q3.y, q3.z, q3.w};
#pragma unroll
        for (int n = 0; n < DS; n++) {
            const float a = __expf(dl * A[n]);
            h[n] = fmaf(a, h[n], du * bv[n]);
        }
    }
    const size_t bd = (size_t)b * DI + d;
#pragma unroll
    for (int n = 0; n < DS; n++) {
        g_hpart[(bd * DS + n) * NCH + c] = h[n];
        g_aP[(bd * DS + n) * NCH + c] = __expf(A[n] * dsum);
    }
}

// ---------------- S2: combine across chunks ----------------
__global__ void k_scan2()
{
    const int idx = blockIdx.x * 256 + threadIdx.x; // (b,d,n) lane
    if (idx >= BATCH * DI * DS) return;
    float h = 0.f;
    const size_t base = (size_t)idx * NCH;
    for (int c = 0; c < NCH; c++) {
        g_hin[base + c] = h;
        h = fmaf(g_aP[base + c], h, g_hpart[base + c]);
    }
}

// ---------------- S3: final scan with correct h_in, emit y ----------------
__global__ void k_scan3(const float* __restrict__ Alog, const float* __restrict__ Dvec)
{
    const int d = blockIdx.x * 128 + threadIdx.x;
    const int c = blockIdx.y;
    const int b = blockIdx.z;

    float A[DS];
#pragma unroll
    for (int n = 0; n < DS; n++) A[n] = -__expf(Alog[d * DS + n]);
    const float Dd = Dvec[d];

    const size_t bd = (size_t)b * DI + d;
    float h[DS];
#pragma unroll
    for (int n = 0; n < DS; n++) h[n] = g_hin[(bd * DS + n) * NCH + c];

    const int l0 = c * CHL;
    const float* dp = g_delta + ((size_t)b * L + l0) * DI + d;
    const float* up = g_u + ((size_t)b * L + l0) * DI + d;
    const float4* bp = reinterpret_cast<const float4*>(g_Bs) + ((size_t)b * L + l0) * 4;
    const float4* cp = reinterpret_cast<const float4*>(g_Cs) + ((size_t)b * L + l0) * 4;
    float* yp = g_y + ((size_t)b * L + l0) * DI + d;

    for (int l = 0; l < CHL; l++) {
        const float dl = dp[(size_t)l * DI];
        const float uu = up[(size_t)l * DI];
        const float du = dl * uu;
        const float4 q0 = bp[l * 4 + 0], q1 = bp[l * 4 + 1],
                     q2 = bp[l * 4 + 2], q3 = bp[l * 4 + 3];
        const float bv[DS] = {q0.x, q0.y, q0.z, q0.w, q1.x, q1.y, q1.z, q1.w,
                              q2.x, q2.y, q2.z, q2.w, q3.x, q3.y, q3.z, q3.w};
        const float4 r0 = cp[l * 4 + 0], r1 = cp[l * 4 + 1],
                     r2 = cp[l * 4 + 2], r3 = cp[l * 4 + 3];
        const float cv[DS] = {r0.x, r0.y, r0.z, r0.w, r1.x, r1.y, r1.z, r1.w,
                              r2.x, r2.y, r2.z, r2.w, r3.x, r3.y, r3.z, r3.w};
        float y = uu * Dd;
#pragma unroll
        for (int n = 0; n < DS; n++) {
            const float a = __expf(dl * A[n]);
            h[n] = fmaf(a, h[n], du * bv[n]);
            y = fmaf(h[n], cv[n], y);
        }
        yp[(size_t)l * DI] = y;
    }
}

// ---------------- K4: LayerNorm + SiLU gate + out GEMM (16 rows/block) ----------------
__global__ void k_out(const float* __restrict__ lng, const float* __restrict__ lnb,
                      const float* __restrict__ Wout, float* __restrict__ out)
{
    __shared__ float yg[16][DI];
    __shared__ float Wt[16][CM];
    const int tid = threadIdx.x; // 256
    const int r0 = blockIdx.x * 16;
    const int warp = tid >> 5, lane = tid & 31;

    // phase 1: each warp normalizes+gates 2 rows
#pragma unroll
    for (int rr = 0; rr < 2; rr++) {
        const int r = warp * 2 + rr;
        const size_t row = (size_t)(r0 + r);
        float v[12];
        float s = 0.f, sq = 0.f;
#pragma unroll
        for (int i = 0; i < 12; i++) {
            v[i] = g_y[row * DI + lane + 32 * i];
            s += v[i];
            sq = fmaf(v[i], v[i], sq);
        }
#pragma unroll
        for (int o = 16; o > 0; o >>= 1) {
            s += __shfl_xor_sync(0xFFFFFFFFu, s, o);
            sq += __shfl_xor_sync(0xFFFFFFFFu, sq, o);
        }
        const float mu = s * (1.f / DI);
        const float var = sq * (1.f / DI) - mu * mu;
        const float rs = rsqrtf(var + 1e-5f);
#pragma unroll
        for (int i = 0; i < 12; i++) {
            const int k = lane + 32 * i;
            const float zn = g_z[row * DI + k];
            const float sig = 1.f / (1.f + __expf(-zn));
            const float g = fmaf((v[i] - mu) * rs, lng[k], lnb[k]);
            yg[r][k] = g * zn * sig;
        }
    }
    __syncthreads();

    // phase 2: 16x384 @ 384x192
    const int tr = tid >> 6;  // 0..3 (row groups of 4)
    const int tc = tid & 63;  // col groups of 3
    float acc[4][3];
#pragma unroll
    for (int r = 0; r < 4; r++)
#pragma unroll
        for (int cc = 0; cc < 3; cc++) acc[r][cc] = 0.f;

    for (int kt = 0; kt < DI; kt += 16) {
#pragma unroll
        for (int i = 0; i < 3; i++) {
            const int e = tid + i * 256;        // 0..767 float4s
            const int kr = e / 48;
            const int c4 = (e % 48) * 4;
            *(float4*)&Wt[kr][c4] = *(const float4*)&Wout[(size_t)(kt + kr) * CM + c4];
        }
        __syncthreads();
#pragma unroll
        for (int k = 0; k < 16; k++) {
            const float w0 = Wt[k][tc * 3 + 0];
            const float w1 = Wt[k][tc * 3 + 1];
            const float w2 = Wt[k][tc * 3 + 2];
#pragma unroll
            for (int r = 0; r < 4; r++) {
                const float a = yg[tr * 4 + r][kt + k];
                acc[r][0] = fmaf(a, w0, acc[r][0]);
                acc[r][1] = fmaf(a, w1, acc[r][1]);
                acc[r][2] = fmaf(a, w2, acc[r][2]);
            }
        }
        __syncthreads();
    }
#pragma unroll
    for (int r = 0; r < 4; r++) {
        const size_t row = (size_t)(r0 + tr * 4 + r);
#pragma unroll
        for (int cc = 0; cc < 3; cc++)
            out[row * CM + tc * 3 + cc] = acc[r][cc];
    }
}

// ---------------- launch ----------------
extern "C" void kernel_launch(void* const* d_in, const int* in_sizes, int n_in,
                              void* d_out, int out_size)
{
    const float* x      = (const float*)d_in[0];
    const float* prompt = (const float*)d_in[1];
    const float* W_in   = (const float*)d_in[2];
    const float* conv_w = (const float*)d_in[3];
    const float* conv_b = (const float*)d_in[4];
    const float* Wx     = (const float*)d_in[5];
    const float* Wdt    = (const float*)d_in[6];
    const float* b_dt   = (const float*)d_in[7];
    const float* A_log  = (const float*)d_in[8];
    const float* Dv     = (const float*)d_in[9];
    const float* Wp     = (const float*)d_in[10];
    const float* ln_g   = (const float*)d_in[11];
    const float* ln_b   = (const float*)d_in[12];
    const float* Wout   = (const float*)d_in[13];
    float* out = (float*)d_out;

    k_gemm_in<<<dim3(M_ROWS / 64, (2 * DI) / 64), 256>>>(x, W_in);
    k_conv<<<dim3(L / 4, DI / 128, BATCH), dim3(128, 4)>>>(conv_w, conv_b);
    k_proj<<<M_ROWS, 128>>>(prompt, Wx, Wdt, b_dt, Wp);
    k_scan1<<<dim3(DI / 128, NCH, BATCH), 128>>>(A_log);
    k_scan2<<<(BATCH * DI * DS + 255) / 256, 256>>>();
    k_scan3<<<dim3(DI / 128, NCH, BATCH), 128>>>(A_log, Dv);
    k_out<<<M_ROWS / 16, 256>>>(ln_g, ln_b, Wout, out);
}

// round 2
// speedup vs baseline: 1.2775x; 1.2775x over previous
#include <cuda_runtime.h>
#include <cstdint>

#define BATCH 4
#define L 4096
#define CM 192
#define DI 384
#define DS 16
#define DTR 12
#define M_ROWS (BATCH * L)   // 16384
#define NCH 128
#define CHL (L / NCH)        // 32
#define BDN (BATCH * DI * DS) // 24576

// ---------------- scratch (device globals; no allocation) ----------------
__device__ float g_xi[(size_t)M_ROWS * DI];
__device__ float g_z[(size_t)M_ROWS * DI];
__device__ float g_u[(size_t)M_ROWS * DI];
__device__ float g_delta[(size_t)M_ROWS * DI];
__device__ float g_dtr[(size_t)M_ROWS * DTR];
__device__ float g_Bs[(size_t)M_ROWS * DS];
__device__ float g_Cs[(size_t)M_ROWS * DS];
__device__ float g_y[(size_t)M_ROWS * DI];
__device__ float g_hpart[(size_t)NCH * BDN];
__device__ float g_aP[(size_t)NCH * BDN];
__device__ float g_hin[(size_t)NCH * BDN];

// ---------------- K1: xz = x @ W_in  (16384 x 768, K=192) ----------------
// 128x128 tile, BK=8, 256 threads, 8x8 per thread (split 4+4 fragments).
__global__ __launch_bounds__(256) void k_gemm_in(const float* __restrict__ X,
                                                 const float* __restrict__ Win)
{
    __shared__ float As[8][128];
    __shared__ float Bs[8][128];
    const int tid = threadIdx.x;
    const int m0 = blockIdx.x * 128;
    const int n0 = blockIdx.y * 128;
    const int tm = tid / 16, tn = tid % 16;

    float acc[8][8];
#pragma unroll
    for (int i = 0; i < 8; i++)
#pragma unroll
        for (int j = 0; j < 8; j++) acc[i][j] = 0.f;

    const int arow = tid / 2, akq = (tid % 2) * 4;
    const int brow = tid / 32, bc4 = (tid % 32) * 4;

    for (int k0 = 0; k0 < CM; k0 += 8) {
        float4 av = *(const float4*)&X[(size_t)(m0 + arow) * CM + k0 + akq];
        As[akq + 0][arow] = av.x;
        As[akq + 1][arow] = av.y;
        As[akq + 2][arow] = av.z;
        As[akq + 3][arow] = av.w;
        *(float4*)&Bs[brow][bc4] =
            *(const float4*)&Win[(size_t)(k0 + brow) * (2 * DI) + n0 + bc4];
        __syncthreads();
#pragma unroll
        for (int k = 0; k < 8; k++) {
            float4 a0 = *(const float4*)&As[k][tm * 4];
            float4 a1 = *(const float4*)&As[k][64 + tm * 4];
            float4 b0 = *(const float4*)&Bs[k][tn * 4];
            float4 b1 = *(const float4*)&Bs[k][64 + tn * 4];
            float a[8] = {a0.x, a0.y, a0.z, a0.w, a1.x, a1.y, a1.z, a1.w};
            float b[8] = {b0.x, b0.y, b0.z, b0.w, b1.x, b1.y, b1.z, b1.w};
#pragma unroll
            for (int i = 0; i < 8; i++)
#pragma unroll
                for (int j = 0; j < 8; j++) acc[i][j] = fmaf(a[i], b[j], acc[i][j]);
        }
        __syncthreads();
    }

    const bool toZ = (n0 >= DI);
#pragma unroll
    for (int ih = 0; ih < 2; ih++)
#pragma unroll
        for (int i = 0; i < 4; i++) {
            const int m = m0 + ih * 64 + tm * 4 + i;
#pragma unroll
            for (int jh = 0; jh < 2; jh++) {
                const int n = n0 + jh * 64 + tn * 4;
                float4 v = make_float4(acc[ih * 4 + i][jh * 4 + 0], acc[ih * 4 + i][jh * 4 + 1],
                                       acc[ih * 4 + i][jh * 4 + 2], acc[ih * 4 + i][jh * 4 + 3]);
                if (toZ) *(float4*)&g_z[(size_t)m * DI + (n - DI)] = v;
                else     *(float4*)&g_xi[(size_t)m * DI + n] = v;
            }
        }
}

// ---------------- conv: depthwise 3x3 + bias + SiLU, smem halo tile ----------------
// block (128 d, 8 w-pixels) on one h row; grid (64h*8wt, 3 d-tiles, 4 b)
__global__ void k_conv(const float* __restrict__ cw, const float* __restrict__ cb)
{
    __shared__ float s[3][10][128];
    const int b = blockIdx.z;
    const int d = blockIdx.y * 128 + threadIdx.x;
    const int h = blockIdx.x >> 3;
    const int w0 = (blockIdx.x & 7) * 8;
    const int tx = threadIdx.x, ty = threadIdx.y;
    const size_t base = (size_t)b * L * DI;

#pragma unroll
    for (int i = 0; i < 4; i++) {
        const int p = ty + 8 * i;
        if (p < 30) {
            const int hh = h + p / 10 - 1;
            const int ww = w0 + p % 10 - 1;
            float v = 0.f;
            if (hh >= 0 && hh < 64 && ww >= 0 && ww < 64)
                v = g_xi[base + (size_t)(hh * 64 + ww) * DI + d];
            s[p / 10][p % 10][tx] = v;
        }
    }
    __syncthreads();

    const float* w9 = cw + d * 9;
    float acc = cb[d];
#pragma unroll
    for (int dh = 0; dh < 3; dh++)
#pragma unroll
        for (int dw = 0; dw < 3; dw++)
            acc = fmaf(s[dh][ty + dw][tx], w9[dh * 3 + dw], acc);

    const float sig = 1.f / (1.f + __expf(-acc));
    g_u[base + (size_t)(h * 64 + w0 + ty) * DI + d] = acc * sig;
}

// ---------------- k_xdbl: x_dbl = u @ Wx  (16384 x 44, K=384) ----------------
// 64x48 tile (44 used), BK=16, 256 threads, 4x3 per thread.
__global__ __launch_bounds__(256) void k_xdbl(const float* __restrict__ Wx)
{
    __shared__ float Us[16][64];
    __shared__ float Wxs[16][48];
    const int tid = threadIdx.x;
    const int m0 = blockIdx.x * 64;
    const int tm = tid / 16, tn = tid % 16;

    float acc[4][3];
#pragma unroll
    for (int i = 0; i < 4; i++)
#pragma unroll
        for (int j = 0; j < 3; j++) acc[i][j] = 0.f;

    const int urow = tid / 4, ukq = (tid % 4) * 4;

    for (int k0 = 0; k0 < DI; k0 += 16) {
        float4 uv = *(const float4*)&g_u[(size_t)(m0 + urow) * DI + k0 + ukq];
        Us[ukq + 0][urow] = uv.x;
        Us[ukq + 1][urow] = uv.y;
        Us[ukq + 2][urow] = uv.z;
        Us[ukq + 3][urow] = uv.w;
#pragma unroll
        for (int i = 0; i < 3; i++) {
            const int f = tid + i * 256;
            const int r = f / 48, c = f % 48;
            Wxs[r][c] = (c < 44) ? Wx[(size_t)(k0 + r) * 44 + c] : 0.f;
        }
        __syncthreads();
#pragma unroll
        for (int k = 0; k < 16; k++) {
            float4 a4 = *(const float4*)&Us[k][tm * 4];
            float a[4] = {a4.x, a4.y, a4.z, a4.w};
            float b0 = Wxs[k][tn * 3 + 0];
            float b1 = Wxs[k][tn * 3 + 1];
            float b2 = Wxs[k][tn * 3 + 2];
#pragma unroll
            for (int i = 0; i < 4; i++) {
                acc[i][0] = fmaf(a[i], b0, acc[i][0]);
                acc[i][1] = fmaf(a[i], b1, acc[i][1]);
                acc[i][2] = fmaf(a[i], b2, acc[i][2]);
            }
        }
        __syncthreads();
    }
#pragma unroll
    for (int i = 0; i < 4; i++) {
        const size_t m = (size_t)(m0 + tm * 4 + i);
#pragma unroll
        for (int j = 0; j < 3; j++) {
            const int c = tn * 3 + j;
            const float v = acc[i][j];
            if (c < DTR)            g_dtr[m * DTR + c] = v;
            else if (c < DTR + DS)  g_Bs[m * DS + (c - DTR)] = v;
            else if (c < 44)        g_Cs[m * DS + (c - DTR - DS)] = v;
        }
    }
}

// ---------------- k_promptC: Cs += prompt @ Wp (16384 x 16, K=192) ----------------
__global__ void k_promptC(const float* __restrict__ prompt, const float* __restrict__ Wp)
{
    __shared__ float p[16 * 192];
    const int tid = threadIdx.x;
    const int row0 = blockIdx.x * 16;
    const float4* src = (const float4*)(prompt + (size_t)row0 * CM);
#pragma unroll
    for (int i = 0; i < 3; i++)
        ((float4*)p)[tid + i * 256] = src[tid + i * 256];
    __syncthreads();

    const int r = tid / 16, n = tid % 16;
    float a0 = 0.f, a1 = 0.f;
    const float* pr = p + r * CM;
#pragma unroll 8
    for (int k = 0; k < CM; k += 2) {
        a0 = fmaf(pr[k],     Wp[(size_t)k * DS + n],       a0);
        a1 = fmaf(pr[k + 1], Wp[(size_t)(k + 1) * DS + n], a1);
    }
    g_Cs[(size_t)(row0 + r) * DS + n] += a0 + a1;
}

// ---------------- k_delta: delta = softplus(dtr @ Wdt + b_dt), 8 rows/block ----------------
__global__ void k_delta(const float* __restrict__ Wdt, const float* __restrict__ bdt)
{
    __shared__ float sd[8][DTR];
    const int tid = threadIdx.x; // 384
    const int row0 = blockIdx.x * 8;
    if (tid < 8 * DTR) sd[tid / DTR][tid % DTR] = g_dtr[(size_t)(row0 + tid / DTR) * DTR + tid % DTR];
    __syncthreads();

    float w[DTR];
#pragma unroll
    for (int r = 0; r < DTR; r++) w[r] = Wdt[(size_t)r * DI + tid];
    const float bb = bdt[tid];
#pragma unroll
    for (int rr = 0; rr < 8; rr++) {
        float acc = bb;
#pragma unroll
        for (int r = 0; r < DTR; r++) acc = fmaf(sd[rr][r], w[r], acc);
        const float sp = acc > 20.f ? acc : log1pf(__expf(acc));
        g_delta[(size_t)(row0 + rr) * DI + tid] = sp;
    }
}

// ---------------- scan helpers ----------------
__device__ __forceinline__ void pow_chain(float e1, float* av)
{
    const float e2 = e1 * e1, e4 = e2 * e2, e8 = e4 * e4;
    av[0] = e1;       av[1] = e2;       av[2] = e2 * e1;   av[3] = e4;
    av[4] = e4 * e1;  av[5] = e4 * e2;  av[6] = e4 * av[2]; av[7] = e8;
    av[8] = e8 * e1;  av[9] = e8 * e2;  av[10] = e8 * av[2]; av[11] = e8 * e4;
    av[12] = e8 * av[4]; av[13] = e8 * av[5]; av[14] = e8 * av[6]; av[15] = e8 * e8;
}

__device__ __forceinline__ bool a_structured(const float* __restrict__ Alog, int d, float& A0)
{
    A0 = -__expf(Alog[(size_t)d * DS]);
    bool ok = true;
#pragma unroll
    for (int n = 1; n < DS; n++) {
        const float Av = -__expf(Alog[(size_t)d * DS + n]);
        ok &= fabsf(Av - (n + 1) * A0) <= 1e-4f * fabsf((n + 1) * A0);
    }
    return ok;
}

// ---------------- S1: per-chunk partial scan (h0 = 0) ----------------
__global__ void k_scan1(const float* __restrict__ Alog)
{
    __shared__ float sB[CHL][DS];
    const int d = blockIdx.x * 128 + threadIdx.x;
    const int c = blockIdx.y;
    const int b = blockIdx.z;
    const int l0 = c * CHL;

    // cooperative load of B chunk
    {
        const float4* src = (const float4*)g_Bs + ((size_t)b * L + l0) * 4;
        ((float4*)sB)[threadIdx.x] = src[threadIdx.x];
    }

    float A0;
    const bool st = a_structured(Alog, d, A0);
    __syncthreads();

    float h[DS];
#pragma unroll
    for (int n = 0; n < DS; n++) h[n] = 0.f;
    float dsum = 0.f;

    const float* dp = g_delta + ((size_t)b * L + l0) * DI + d;
    const float* up = g_u + ((size_t)b * L + l0) * DI + d;

    if (st) {
        for (int l = 0; l < CHL; l++) {
            const float dl = dp[(size_t)l * DI];
            const float du = dl * up[(size_t)l * DI];
            dsum += dl;
            float av[DS];
            pow_chain(__expf(dl * A0), av);
#pragma unroll
            for (int n = 0; n < DS; n++) h[n] = fmaf(av[n], h[n], du * sB[l][n]);
        }
        float av[DS];
        pow_chain(__expf(dsum * A0), av);
        const size_t base = (size_t)c * BDN + ((size_t)b * DI + d) * DS;
#pragma unroll
        for (int n = 0; n < DS; n++) {
            g_hpart[base + n] = h[n];
            g_aP[base + n] = av[n];
        }
    } else {
        float A[DS];
#pragma unroll
        for (int n = 0; n < DS; n++) A[n] = -__expf(Alog[(size_t)d * DS + n]);
        for (int l = 0; l < CHL; l++) {
            const float dl = dp[(size_t)l * DI];
            const float du = dl * up[(size_t)l * DI];
            dsum += dl;
#pragma unroll
            for (int n = 0; n < DS; n++)
                h[n] = fmaf(__expf(dl * A[n]), h[n], du * sB[l][n]);
        }
        const size_t base = (size_t)c * BDN + ((size_t)b * DI + d) * DS;
#pragma unroll
        for (int n = 0; n < DS; n++) {
            g_hpart[base + n] = h[n];
            g_aP[base + n] = __expf(A[n] * dsum);
        }
    }
}

// ---------------- S2: combine across chunks ----------------
__global__ void k_scan2()
{
    const int idx = blockIdx.x * 256 + threadIdx.x;
    if (idx >= BDN) return;
    float h = 0.f;
    for (int c = 0; c < NCH; c++) {
        const size_t o = (size_t)c * BDN + idx;
        g_hin[o] = h;
        h = fmaf(g_aP[o], h, g_hpart[o]);
    }
}

// ---------------- S3: final scan with correct h_in, emit y ----------------
__global__ void k_scan3(const float* __restrict__ Alog, const float* __restrict__ Dvec)
{
    __shared__ float sB[CHL][DS];
    __shared__ float sC[CHL][DS];
    const int d = blockIdx.x * 128 + threadIdx.x;
    const int c = blockIdx.y;
    const int b = blockIdx.z;
    const int l0 = c * CHL;

    {
        const float4* srcB = (const float4*)g_Bs + ((size_t)b * L + l0) * 4;
        const float4* srcC = (const float4*)g_Cs + ((size_t)b * L + l0) * 4;
        ((float4*)sB)[threadIdx.x] = srcB[threadIdx.x];
        ((float4*)sC)[threadIdx.x] = srcC[threadIdx.x];
    }

    float A0;
    const bool st = a_structured(Alog, d, A0);
    const float Dd = Dvec[d];
    __syncthreads();

    float h[DS];
    {
        const size_t base = (size_t)c * BDN + ((size_t)b * DI + d) * DS;
#pragma unroll
        for (int n = 0; n < DS; n++) h[n] = g_hin[base + n];
    }

    const float* dp = g_delta + ((size_t)b * L + l0) * DI + d;
    const float* up = g_u + ((size_t)b * L + l0) * DI + d;
    float* yp = g_y + ((size_t)b * L + l0) * DI + d;

    if (st) {
        for (int l = 0; l < CHL; l++) {
            const float dl = dp[(size_t)l * DI];
            const float uu = up[(size_t)l * DI];
            const float du = dl * uu;
            float av[DS];
            pow_chain(__expf(dl * A0), av);
            float y = uu * Dd;
#pragma unroll
            for (int n = 0; n < DS; n++) {
                h[n] = fmaf(av[n], h[n], du * sB[l][n]);
                y = fmaf(h[n], sC[l][n], y);
            }
            yp[(size_t)l * DI] = y;
        }
    } else {
        float A[DS];
#pragma unroll
        for (int n = 0; n < DS; n++) A[n] = -__expf(Alog[(size_t)d * DS + n]);
        for (int l = 0; l < CHL; l++) {
            const float dl = dp[(size_t)l * DI];
            const float uu = up[(size_t)l * DI];
            const float du = dl * uu;
            float y = uu * Dd;
#pragma unroll
            for (int n = 0; n < DS; n++) {
                h[n] = fmaf(__expf(dl * A[n]), h[n], du * sB[l][n]);
                y = fmaf(h[n], sC[l][n], y);
            }
            yp[(size_t)l * DI] = y;
        }
    }
}

// ---------------- K4: LayerNorm + SiLU gate + out GEMM (16 rows/block) ----------------
__global__ void k_out(const float* __restrict__ lng, const float* __restrict__ lnb,
                      const float* __restrict__ Wout, float* __restrict__ out)
{
    __shared__ float yg[16][DI];
    __shared__ float Wt[16][CM];
    const int tid = threadIdx.x; // 256
    const int r0 = blockIdx.x * 16;
    const int warp = tid >> 5, lane = tid & 31;

#pragma unroll
    for (int rr = 0; rr < 2; rr++) {
        const int r = warp * 2 + rr;
        const size_t row = (size_t)(r0 + r);
        float v[12];
        float s = 0.f, sq = 0.f;
#pragma unroll
        for (int i = 0; i < 12; i++) {
            v[i] = g_y[row * DI + lane + 32 * i];
            s += v[i];
            sq = fmaf(v[i], v[i], sq);
        }
#pragma unroll
        for (int o = 16; o > 0; o >>= 1) {
            s += __shfl_xor_sync(0xFFFFFFFFu, s, o);
            sq += __shfl_xor_sync(0xFFFFFFFFu, sq, o);
        }
        const float mu = s * (1.f / DI);
        const float var = sq * (1.f / DI) - mu * mu;
        const float rs = rsqrtf(var + 1e-5f);
#pragma unroll
        for (int i = 0; i < 12; i++) {
            const int k = lane + 32 * i;
            const float zn = g_z[row * DI + k];
            const float sig = 1.f / (1.f + __expf(-zn));
            const float g = fmaf((v[i] - mu) * rs, lng[k], lnb[k]);
            yg[r][k] = g * zn * sig;
        }
    }
    __syncthreads();

    const int tr = tid >> 6;
    const int tc = tid & 63;
    float acc[4][3];
#pragma unroll
    for (int r = 0; r < 4; r++)
#pragma unroll
        for (int cc = 0; cc < 3; cc++) acc[r][cc] = 0.f;

    for (int kt = 0; kt < DI; kt += 16) {
#pragma unroll
        for (int i = 0; i < 3; i++) {
            const int e = tid + i * 256;
            const int kr = e / 48;
            const int c4 = (e % 48) * 4;
            *(float4*)&Wt[kr][c4] = *(const float4*)&Wout[(size_t)(kt + kr) * CM + c4];
        }
        __syncthreads();
#pragma unroll
        for (int k = 0; k < 16; k++) {
            const float w0 = Wt[k][tc * 3 + 0];
            const float w1 = Wt[k][tc * 3 + 1];
            const float w2 = Wt[k][tc * 3 + 2];
#pragma unroll
            for (int r = 0; r < 4; r++) {
                const float a = yg[tr * 4 + r][kt + k];
                acc[r][0] = fmaf(a, w0, acc[r][0]);
                acc[r][1] = fmaf(a, w1, acc[r][1]);
                acc[r][2] = fmaf(a, w2, acc[r][2]);
            }
        }
        __syncthreads();
    }
#pragma unroll
    for (int r = 0; r < 4; r++) {
        const size_t row = (size_t)(r0 + tr * 4 + r);
#pragma unroll
        for (int cc = 0; cc < 3; cc++)
            out[row * CM + tc * 3 + cc] = acc[r][cc];
    }
}

// ---------------- launch ----------------
extern "C" void kernel_launch(void* const* d_in, const int* in_sizes, int n_in,
                              void* d_out, int out_size)
{
    const float* x      = (const float*)d_in[0];
    const float* prompt = (const float*)d_in[1];
    const float* W_in   = (const float*)d_in[2];
    const float* conv_w = (const float*)d_in[3];
    const float* conv_b = (const float*)d_in[4];
    const float* Wx     = (const float*)d_in[5];
    const float* Wdt    = (const float*)d_in[6];
    const float* b_dt   = (const float*)d_in[7];
    const float* A_log  = (const float*)d_in[8];
    const float* Dv     = (const float*)d_in[9];
    const float* Wp     = (const float*)d_in[10];
    const float* ln_g   = (const float*)d_in[11];
    const float* ln_b   = (const float*)d_in[12];
    const float* Wout   = (const float*)d_in[13];
    float* out = (float*)d_out;

    k_gemm_in<<<dim3(M_ROWS / 128, (2 * DI) / 128), 256>>>(x, W_in);
    k_conv<<<dim3(64 * 8, DI / 128, BATCH), dim3(128, 8)>>>(conv_w, conv_b);
    k_xdbl<<<M_ROWS / 64, 256>>>(Wx);
    k_promptC<<<M_ROWS / 16, 256>>>(prompt, Wp);
    k_delta<<<M_ROWS / 8, DI>>>(Wdt, b_dt);
    k_scan1<<<dim3(DI / 128, NCH, BATCH), 128>>>(A_log);
    k_scan2<<<(BDN + 255) / 256, 256>>>();
    k_scan3<<<dim3(DI / 128, NCH, BATCH), 128>>>(A_log, Dv);
    k_out<<<M_ROWS / 16, 256>>>(ln_g, ln_b, Wout, out);
}

// round 4
// speedup vs baseline: 1.3510x; 1.0576x over previous
#include <cuda_runtime.h>
#include <cuda_bf16.h>
#include <cstdint>

#define BATCH 4
#define L 4096
#define CM 192
#define DI 384
#define DS 16
#define DTR 12
#define M_ROWS (BATCH * L)   // 16384
#define NCH 128
#define CHL (L / NCH)        // 32
#define BDN (BATCH * DI * DS) // 24576
#define NX (2 * DI)          // 768

// ---------------- scratch (device globals; no allocation) ----------------
__device__ float g_xi[(size_t)M_ROWS * DI];
__device__ float g_z[(size_t)M_ROWS * DI];
__device__ float g_u[(size_t)M_ROWS * DI];
__device__ float g_delta[(size_t)M_ROWS * DI];
__device__ float g_dtr[(size_t)M_ROWS * DTR];
__device__ float g_Bs[(size_t)M_ROWS * DS];
__device__ float g_Cs[(size_t)M_ROWS * DS];
__device__ float g_y[(size_t)M_ROWS * DI];
__device__ float g_hpart[(size_t)NCH * BDN];
__device__ float g_aP[(size_t)NCH * BDN];
__device__ float g_hin[(size_t)NCH * BDN];
__device__ __nv_bfloat16 g_xhi[(size_t)M_ROWS * CM];
__device__ __nv_bfloat16 g_xlo[(size_t)M_ROWS * CM];
__device__ __nv_bfloat16 g_whi[(size_t)NX * CM];   // transposed: [n][k]
__device__ __nv_bfloat16 g_wlo[(size_t)NX * CM];

// ---------------- split kernels: fp32 -> bf16 hi/lo ----------------
__global__ void k_split_x(const float* __restrict__ X)
{
    const size_t i = ((size_t)blockIdx.x * 256 + threadIdx.x) * 4;
    float4 v = *(const float4*)&X[i];
    __nv_bfloat16 h0 = __float2bfloat16(v.x), h1 = __float2bfloat16(v.y),
                  h2 = __float2bfloat16(v.z), h3 = __float2bfloat16(v.w);
    __nv_bfloat16 l0 = __float2bfloat16(v.x - __bfloat162float(h0));
    __nv_bfloat16 l1 = __float2bfloat16(v.y - __bfloat162float(h1));
    __nv_bfloat16 l2 = __float2bfloat16(v.z - __bfloat162float(h2));
    __nv_bfloat16 l3 = __float2bfloat16(v.w - __bfloat162float(h3));
    __nv_bfloat162* ph = (__nv_bfloat162*)&g_xhi[i];
    __nv_bfloat162* pl = (__nv_bfloat162*)&g_xlo[i];
    ph[0] = __nv_bfloat162(h0, h1); ph[1] = __nv_bfloat162(h2, h3);
    pl[0] = __nv_bfloat162(l0, l1); pl[1] = __nv_bfloat162(l2, l3);
}

__global__ void k_split_w(const float* __restrict__ Win)
{
    const int i = blockIdx.x * 256 + threadIdx.x;
    if (i >= CM * NX) return;
    const int k = i / NX, n = i % NX;
    const float v = Win[i];
    const __nv_bfloat16 h = __float2bfloat16(v);
    g_whi[(size_t)n * CM + k] = h;
    g_wlo[(size_t)n * CM + k] = __float2bfloat16(v - __bfloat162float(h));
}

// ---------------- K1: xz = x @ W_in via bf16x3 mma.sync ----------------
// 128x128 CTA tile, 8 warps of 32x64, K chunked at 32, pitch-padded smem.
#define KP 40   // bf16 row pitch (80B): conflict-free fragment loads

__device__ __forceinline__ void mma_bf16(float* d, const uint32_t* a, const uint32_t* b)
{
    asm volatile(
        "mma.sync.aligned.m16n8k16.row.col.f32.bf16.bf16.f32 "
        "{%0,%1,%2,%3}, {%4,%5,%6,%7}, {%8,%9}, {%0,%1,%2,%3};"
        : "+f"(d[0]), "+f"(d[1]), "+f"(d[2]), "+f"(d[3])
        : "r"(a[0]), "r"(a[1]), "r"(a[2]), "r"(a[3]), "r"(b[0]), "r"(b[1]));
}

__global__ __launch_bounds__(256) void k_gemm_mma()
{
    __shared__ __nv_bfloat16 sAh[128][KP], sAl[128][KP], sBh[128][KP], sBl[128][KP];
    const int tid = threadIdx.x;
    const int wid = tid >> 5, t = tid & 31;
    const int m0 = blockIdx.x * 128, n0 = blockIdx.y * 128;
    const int wr = wid & 3, wc = wid >> 2;          // warp tile: rows wr*32, cols wc*64
    const int g = t >> 2, c2 = (t & 3) * 2;

    float acc[2][8][4];
#pragma unroll
    for (int mt = 0; mt < 2; mt++)
#pragma unroll
        for (int nt = 0; nt < 8; nt++)
#pragma unroll
            for (int e = 0; e < 4; e++) acc[mt][nt][e] = 0.f;

    const int lr = tid >> 1;            // load row 0..127
    const int lh = (tid & 1) * 16;      // 16 bf16 half

    for (int kc = 0; kc < CM; kc += 32) {
        {
            const __nv_bfloat16* ah = g_xhi + (size_t)(m0 + lr) * CM + kc + lh;
            const __nv_bfloat16* al = g_xlo + (size_t)(m0 + lr) * CM + kc + lh;
            const __nv_bfloat16* bh = g_whi + (size_t)(n0 + lr) * CM + kc + lh;
            const __nv_bfloat16* bl = g_wlo + (size_t)(n0 + lr) * CM + kc + lh;
            *(float4*)&sAh[lr][lh]     = *(const float4*)(ah);
            *(float4*)&sAh[lr][lh + 8] = *(const float4*)(ah + 8);
            *(float4*)&sAl[lr][lh]     = *(const float4*)(al);
            *(float4*)&sAl[lr][lh + 8] = *(const float4*)(al + 8);
            *(float4*)&sBh[lr][lh]     = *(const float4*)(bh);
            *(float4*)&sBh[lr][lh + 8] = *(const float4*)(bh + 8);
            *(float4*)&sBl[lr][lh]     = *(const float4*)(bl);
            *(float4*)&sBl[lr][lh + 8] = *(const float4*)(bl + 8);
        }
        __syncthreads();

#pragma unroll
        for (int ks = 0; ks < 2; ks++) {
            const int K0 = ks * 16;
            uint32_t ahf[2][4], alf[2][4];
#pragma unroll
            for (int mt = 0; mt < 2; mt++) {
                const int R = wr * 32 + mt * 16;
                ahf[mt][0] = *(const uint32_t*)&sAh[R + g][K0 + c2];
                ahf[mt][1] = *(const uint32_t*)&sAh[R + g + 8][K0 + c2];
                ahf[mt][2] = *(const uint32_t*)&sAh[R + g][K0 + c2 + 8];
                ahf[mt][3] = *(const uint32_t*)&sAh[R + g + 8][K0 + c2 + 8];
                alf[mt][0] = *(const uint32_t*)&sAl[R + g][K0 + c2];
                alf[mt][1] = *(const uint32_t*)&sAl[R + g + 8][K0 + c2];
                alf[mt][2] = *(const uint32_t*)&sAl[R + g][K0 + c2 + 8];
                alf[mt][3] = *(const uint32_t*)&sAl[R + g + 8][K0 + c2 + 8];
            }
#pragma unroll
            for (int nt = 0; nt < 8; nt++) {
                const int N = wc * 64 + nt * 8;
                uint32_t bhf[2], blf[2];
                bhf[0] = *(const uint32_t*)&sBh[N + g][K0 + c2];
                bhf[1] = *(const uint32_t*)&sBh[N + g][K0 + c2 + 8];
                blf[0] = *(const uint32_t*)&sBl[N + g][K0 + c2];
                blf[1] = *(const uint32_t*)&sBl[N + g][K0 + c2 + 8];
#pragma unroll
                for (int mt = 0; mt < 2; mt++) {
                    mma_bf16(acc[mt][nt], ahf[mt], bhf);
                    mma_bf16(acc[mt][nt], ahf[mt], blf);
                    mma_bf16(acc[mt][nt], alf[mt], bhf);
                }
            }
        }
        __syncthreads();
    }

    // epilogue: direct float2 stores
    const bool toZ = (n0 >= DI);
#pragma unroll
    for (int mt = 0; mt < 2; mt++) {
#pragma unroll
        for (int nt = 0; nt < 8; nt++) {
            int nc = n0 + wc * 64 + nt * 8 + c2;
            if (toZ) nc -= DI;
            const int r0 = m0 + wr * 32 + mt * 16 + g;
            float* base = toZ ? g_z : g_xi;
            *(float2*)&base[(size_t)r0 * DI + nc] =
                make_float2(acc[mt][nt][0], acc[mt][nt][1]);
            *(float2*)&base[(size_t)(r0 + 8) * DI + nc] =
                make_float2(acc[mt][nt][2], acc[mt][nt][3]);
        }
    }
}

// ---------------- conv: depthwise 3x3 + bias + SiLU, smem halo tile ----------------
__global__ void k_conv(const float* __restrict__ cw, const float* __restrict__ cb)
{
    __shared__ float s[3][10][128];
    const int b = blockIdx.z;
    const int d = blockIdx.y * 128 + threadIdx.x;
    const int h = blockIdx.x >> 3;
    const int w0 = (blockIdx.x & 7) * 8;
    const int tx = threadIdx.x, ty = threadIdx.y;
    const size_t base = (size_t)b * L * DI;

#pragma unroll
    for (int i = 0; i < 4; i++) {
        const int p = ty + 8 * i;
        if (p < 30) {
            const int hh = h + p / 10 - 1;
            const int ww = w0 + p % 10 - 1;
            float v = 0.f;
            if (hh >= 0 && hh < 64 && ww >= 0 && ww < 64)
                v = g_xi[base + (size_t)(hh * 64 + ww) * DI + d];
            s[p / 10][p % 10][tx] = v;
        }
    }
    __syncthreads();

    const float* w9 = cw + d * 9;
    float acc = cb[d];
#pragma unroll
    for (int dh = 0; dh < 3; dh++)
#pragma unroll
        for (int dw = 0; dw < 3; dw++)
            acc = fmaf(s[dh][ty + dw][tx], w9[dh * 3 + dw], acc);

    const float sig = 1.f / (1.f + __expf(-acc));
    g_u[base + (size_t)(h * 64 + w0 + ty) * DI + d] = acc * sig;
}

// ---------------- k_xdbl: x_dbl = u @ Wx  (16384 x 44, K=384) ----------------
__global__ __launch_bounds__(256) void k_xdbl(const float* __restrict__ Wx)
{
    __shared__ float Us[16][64];
    __shared__ float Wxs[16][48];
    const int tid = threadIdx.x;
    const int m0 = blockIdx.x * 64;
    const int tm = tid / 16, tn = tid % 16;

    float acc[4][3];
#pragma unroll
    for (int i = 0; i < 4; i++)
#pragma unroll
        for (int j = 0; j < 3; j++) acc[i][j] = 0.f;

    const int urow = tid / 4, ukq = (tid % 4) * 4;

    for (int k0 = 0; k0 < DI; k0 += 16) {
        float4 uv = *(const float4*)&g_u[(size_t)(m0 + urow) * DI + k0 + ukq];
        Us[ukq + 0][urow] = uv.x;
        Us[ukq + 1][urow] = uv.y;
        Us[ukq + 2][urow] = uv.z;
        Us[ukq + 3][urow] = uv.w;
#pragma unroll
        for (int i = 0; i < 3; i++) {
            const int f = tid + i * 256;
            const int rr = f / 48, c = f % 48;
            Wxs[rr][c] = (c < 44) ? Wx[(size_t)(k0 + rr) * 44 + c] : 0.f;
        }
        __syncthreads();
#pragma unroll
        for (int k = 0; k < 16; k++) {
            float4 a4 = *(const float4*)&Us[k][tm * 4];
            float a[4] = {a4.x, a4.y, a4.z, a4.w};
            float b0 = Wxs[k][tn * 3 + 0];
            float b1 = Wxs[k][tn * 3 + 1];
            float b2 = Wxs[k][tn * 3 + 2];
#pragma unroll
            for (int i = 0; i < 4; i++) {
                acc[i][0] = fmaf(a[i], b0, acc[i][0]);
                acc[i][1] = fmaf(a[i], b1, acc[i][1]);
                acc[i][2] = fmaf(a[i], b2, acc[i][2]);
            }
        }
        __syncthreads();
    }
#pragma unroll
    for (int i = 0; i < 4; i++) {
        const size_t m = (size_t)(m0 + tm * 4 + i);
#pragma unroll
        for (int j = 0; j < 3; j++) {
            const int c = tn * 3 + j;
            const float v = acc[i][j];
            if (c < DTR)            g_dtr[m * DTR + c] = v;
            else if (c < DTR + DS)  g_Bs[m * DS + (c - DTR)] = v;
            else if (c < 44)        g_Cs[m * DS + (c - DTR - DS)] = v;
        }
    }
}

// ---------------- k_promptC: Cs += prompt @ Wp (16384 x 16, K=192) ----------------
__global__ void k_promptC(const float* __restrict__ prompt, const float* __restrict__ Wp)
{
    __shared__ float p[16 * 192];
    const int tid = threadIdx.x;
    const int row0 = blockIdx.x * 16;
    const float4* src = (const float4*)(prompt + (size_t)row0 * CM);
#pragma unroll
    for (int i = 0; i < 3; i++)
        ((float4*)p)[tid + i * 256] = src[tid + i * 256];
    __syncthreads();

    const int r = tid / 16, n = tid % 16;
    float a0 = 0.f, a1 = 0.f;
    const float* pr = p + r * CM;
#pragma unroll 8
    for (int k = 0; k < CM; k += 2) {
        a0 = fmaf(pr[k],     Wp[(size_t)k * DS + n],       a0);
        a1 = fmaf(pr[k + 1], Wp[(size_t)(k + 1) * DS + n], a1);
    }
    g_Cs[(size_t)(row0 + r) * DS + n] += a0 + a1;
}

// ---------------- k_delta ----------------
__global__ void k_delta(const float* __restrict__ Wdt, const float* __restrict__ bdt)
{
    __shared__ float sd[8][DTR];
    const int tid = threadIdx.x; // 384
    const int row0 = blockIdx.x * 8;
    if (tid < 8 * DTR) sd[tid / DTR][tid % DTR] = g_dtr[(size_t)(row0 + tid / DTR) * DTR + tid % DTR];
    __syncthreads();

    float w[DTR];
#pragma unroll
    for (int rr = 0; rr < DTR; rr++) w[rr] = Wdt[(size_t)rr * DI + tid];
    const float bb = bdt[tid];
#pragma unroll
    for (int rr = 0; rr < 8; rr++) {
        float acc = bb;
#pragma unroll
        for (int r2 = 0; r2 < DTR; r2++) acc = fmaf(sd[rr][r2], w[r2], acc);
        const float sp = acc > 20.f ? acc : log1pf(__expf(acc));
        g_delta[(size_t)(row0 + rr) * DI + tid] = sp;
    }
}

// ---------------- scan helpers ----------------
__device__ __forceinline__ void pow_chain(float e1, float* av)
{
    const float e2 = e1 * e1, e4 = e2 * e2, e8 = e4 * e4;
    av[0] = e1;       av[1] = e2;       av[2] = e2 * e1;   av[3] = e4;
    av[4] = e4 * e1;  av[5] = e4 * e2;  av[6] = e4 * av[2]; av[7] = e8;
    av[8] = e8 * e1;  av[9] = e8 * e2;  av[10] = e8 * av[2]; av[11] = e8 * e4;
    av[12] = e8 * av[4]; av[13] = e8 * av[5]; av[14] = e8 * av[6]; av[15] = e8 * e8;
}

__device__ __forceinline__ bool a_structured(const float* __restrict__ Alog, int d, float& A0)
{
    A0 = -__expf(Alog[(size_t)d * DS]);
    bool ok = true;
#pragma unroll
    for (int n = 1; n < DS; n++) {
        const float Av = -__expf(Alog[(size_t)d * DS + n]);
        ok &= fabsf(Av - (n + 1) * A0) <= 1e-4f * fabsf((n + 1) * A0);
    }
    return ok;
}

// ---------------- S1 ----------------
__global__ void k_scan1(const float* __restrict__ Alog)
{
    __shared__ float sB[CHL][DS];
    const int d = blockIdx.x * 128 + threadIdx.x;
    const int c = blockIdx.y;
    const int b = blockIdx.z;
    const int l0 = c * CHL;

    {
        const float4* src = (const float4*)g_Bs + ((size_t)b * L + l0) * 4;
        ((float4*)sB)[threadIdx.x] = src[threadIdx.x];
    }

    float A0;
    const bool st = a_structured(Alog, d, A0);
    __syncthreads();

    float h[DS];
#pragma unroll
    for (int n = 0; n < DS; n++) h[n] = 0.f;
    float dsum = 0.f;

    const float* dp = g_delta + ((size_t)b * L + l0) * DI + d;
    const float* up = g_u + ((size_t)b * L + l0) * DI + d;

    if (st) {
        for (int l = 0; l < CHL; l++) {
            const float dl = dp[(size_t)l * DI];
            const float du = dl * up[(size_t)l * DI];
            dsum += dl;
            float av[DS];
            pow_chain(__expf(dl * A0), av);
#pragma unroll
            for (int n = 0; n < DS; n++) h[n] = fmaf(av[n], h[n], du * sB[l][n]);
        }
        float av[DS];
        pow_chain(__expf(dsum * A0), av);
        const size_t base = (size_t)c * BDN + ((size_t)b * DI + d) * DS;
#pragma unroll
        for (int n = 0; n < DS; n++) {
            g_hpart[base + n] = h[n];
            g_aP[base + n] = av[n];
        }
    } else {
        float A[DS];
#pragma unroll
        for (int n = 0; n < DS; n++) A[n] = -__expf(Alog[(size_t)d * DS + n]);
        for (int l = 0; l < CHL; l++) {
            const float dl = dp[(size_t)l * DI];
            const float du = dl * up[(size_t)l * DI];
            dsum += dl;
#pragma unroll
            for (int n = 0; n < DS; n++)
                h[n] = fmaf(__expf(dl * A[n]), h[n], du * sB[l][n]);
        }
        const size_t base = (size_t)c * BDN + ((size_t)b * DI + d) * DS;
#pragma unroll
        for (int n = 0; n < DS; n++) {
            g_hpart[base + n] = h[n];
            g_aP[base + n] = __expf(A[n] * dsum);
        }
    }
}

// ---------------- S2 ----------------
__global__ void k_scan2()
{
    const int idx = blockIdx.x * 256 + threadIdx.x;
    if (idx >= BDN) return;
    float h = 0.f;
    for (int c = 0; c < NCH; c++) {
        const size_t o = (size_t)c * BDN + idx;
        g_hin[o] = h;
        h = fmaf(g_aP[o], h, g_hpart[o]);
    }
}

// ---------------- S3 ----------------
__global__ void k_scan3(const float* __restrict__ Alog, const float* __restrict__ Dvec)
{
    __shared__ float sB[CHL][DS];
    __shared__ float sC[CHL][DS];
    const int d = blockIdx.x * 128 + threadIdx.x;
    const int c = blockIdx.y;
    const int b = blockIdx.z;
    const int l0 = c * CHL;

    {
        const float4* srcB = (const float4*)g_Bs + ((size_t)b * L + l0) * 4;
        const float4* srcC = (const float4*)g_Cs + ((size_t)b * L + l0) * 4;
        ((float4*)sB)[threadIdx.x] = srcB[threadIdx.x];
        ((float4*)sC)[threadIdx.x] = srcC[threadIdx.x];
    }

    float A0;
    const bool st = a_structured(Alog, d, A0);
    const float Dd = Dvec[d];
    __syncthreads();

    float h[DS];
    {
        const size_t base = (size_t)c * BDN + ((size_t)b * DI + d) * DS;
#pragma unroll
        for (int n = 0; n < DS; n++) h[n] = g_hin[base + n];
    }

    const float* dp = g_delta + ((size_t)b * L + l0) * DI + d;
    const float* up = g_u + ((size_t)b * L + l0) * DI + d;
    float* yp = g_y + ((size_t)b * L + l0) * DI + d;

    if (st) {
        for (int l = 0; l < CHL; l++) {
            const float dl = dp[(size_t)l * DI];
            const float uu = up[(size_t)l * DI];
            const float du = dl * uu;
            float av[DS];
            pow_chain(__expf(dl * A0), av);
            float y = uu * Dd;
#pragma unroll
            for (int n = 0; n < DS; n++) {
                h[n] = fmaf(av[n], h[n], du * sB[l][n]);
                y = fmaf(h[n], sC[l][n], y);
            }
            yp[(size_t)l * DI] = y;
        }
    } else {
        float A[DS];
#pragma unroll
        for (int n = 0; n < DS; n++) A[n] = -__expf(Alog[(size_t)d * DS + n]);
        for (int l = 0; l < CHL; l++) {
            const float dl = dp[(size_t)l * DI];
            const float uu = up[(size_t)l * DI];
            const float du = dl * uu;
            float y = uu * Dd;
#pragma unroll
            for (int n = 0; n < DS; n++) {
                h[n] = fmaf(__expf(dl * A[n]), h[n], du * sB[l][n]);
                y = fmaf(h[n], sC[l][n], y);
            }
            yp[(size_t)l * DI] = y;
        }
    }
}

// ---------------- K4: LayerNorm + SiLU gate + out GEMM ----------------
__global__ void k_out(const float* __restrict__ lng, const float* __restrict__ lnb,
                      const float* __restrict__ Wout, float* __restrict__ out)
{
    __shared__ float yg[16][DI];
    __shared__ float Wt[16][CM];
    const int tid = threadIdx.x; // 256
    const int r0 = blockIdx.x * 16;
    const int warp = tid >> 5, lane = tid & 31;

#pragma unroll
    for (int rr = 0; rr < 2; rr++) {
        const int r = warp * 2 + rr;
        const size_t row = (size_t)(r0 + r);
        float v[12];
        float s = 0.f, sq = 0.f;
#pragma unroll
        for (int i = 0; i < 12; i++) {
            v[i] = g_y[row * DI + lane + 32 * i];
            s += v[i];
            sq = fmaf(v[i], v[i], sq);
        }
#pragma unroll
        for (int o = 16; o > 0; o >>= 1) {
            s += __shfl_xor_sync(0xFFFFFFFFu, s, o);
            sq += __shfl_xor_sync(0xFFFFFFFFu, sq, o);
        }
        const float mu = s * (1.f / DI);
        const float var = sq * (1.f / DI) - mu * mu;
        const float rs = rsqrtf(var + 1e-5f);
#pragma unroll
        for (int i = 0; i < 12; i++) {
            const int k = lane + 32 * i;
            const float zn = g_z[row * DI + k];
            const float sig = 1.f / (1.f + __expf(-zn));
            const float g = fmaf((v[i] - mu) * rs, lng[k], lnb[k]);
            yg[r][k] = g * zn * sig;
        }
    }
    __syncthreads();

    const int tr = tid >> 6;
    const int tc = tid & 63;
    float acc[4][3];
#pragma unroll
    for (int r = 0; r < 4; r++)
#pragma unroll
        for (int cc = 0; cc < 3; cc++) acc[r][cc] = 0.f;

    for (int kt = 0; kt < DI; kt += 16) {
#pragma unroll
        for (int i = 0; i < 3; i++) {
            const int e = tid + i * 256;
            const int kr = e / 48;
            const int c4 = (e % 48) * 4;
            *(float4*)&Wt[kr][c4] = *(const float4*)&Wout[(size_t)(kt + kr) * CM + c4];
        }
        __syncthreads();
#pragma unroll
        for (int k = 0; k < 16; k++) {
            const float w0 = Wt[k][tc * 3 + 0];
            const float w1 = Wt[k][tc * 3 + 1];
            const float w2 = Wt[k][tc * 3 + 2];
#pragma unroll
            for (int r = 0; r < 4; r++) {
                const float a = yg[tr * 4 + r][kt + k];
                acc[r][0] = fmaf(a, w0, acc[r][0]);
                acc[r][1] = fmaf(a, w1, acc[r][1]);
                acc[r][2] = fmaf(a, w2, acc[r][2]);
            }
        }
        __syncthreads();
    }
#pragma unroll
    for (int r = 0; r < 4; r++) {
        const size_t row = (size_t)(r0 + tr * 4 + r);
#pragma unroll
        for (int cc = 0; cc < 3; cc++)
            out[row * CM + tc * 3 + cc] = acc[r][cc];
    }
}

// ---------------- launch ----------------
extern "C" void kernel_launch(void* const* d_in, const int* in_sizes, int n_in,
                              void* d_out, int out_size)
{
    const float* x      = (const float*)d_in[0];
    const float* prompt = (const float*)d_in[1];
    const float* W_in   = (const float*)d_in[2];
    const float* conv_w = (const float*)d_in[3];
    const float* conv_b = (const float*)d_in[4];
    const float* Wx     = (const float*)d_in[5];
    const float* Wdt    = (const float*)d_in[6];
    const float* b_dt   = (const float*)d_in[7];
    const float* A_log  = (const float*)d_in[8];
    const float* Dv     = (const float*)d_in[9];
    const float* Wp     = (const float*)d_in[10];
    const float* ln_g   = (const float*)d_in[11];
    const float* ln_b   = (const float*)d_in[12];
    const float* Wout   = (const float*)d_in[13];
    float* out = (float*)d_out;

    k_split_x<<<(M_ROWS * CM) / (256 * 4), 256>>>(x);
    k_split_w<<<(CM * NX + 255) / 256, 256>>>(W_in);
    k_gemm_mma<<<dim3(M_ROWS / 128, NX / 128), 256>>>();
    k_conv<<<dim3(64 * 8, DI / 128, BATCH), dim3(128, 8)>>>(conv_w, conv_b);
    k_xdbl<<<M_ROWS / 64, 256>>>(Wx);
    k_promptC<<<M_ROWS / 16, 256>>>(prompt, Wp);
    k_delta<<<M_ROWS / 8, DI>>>(Wdt, b_dt);
    k_scan1<<<dim3(DI / 128, NCH, BATCH), 128>>>(A_log);
    k_scan2<<<(BDN + 255) / 256, 256>>>();
    k_scan3<<<dim3(DI / 128, NCH, BATCH), 128>>>(A_log, Dv);
    k_out<<<M_ROWS / 16, 256>>>(ln_g, ln_b, Wout, out);
}

// round 5
// speedup vs baseline: 1.4316x; 1.0596x over previous
#include <cuda_runtime.h>
#include <cuda_bf16.h>
#include <cstdint>

#define BATCH 4
#define L 4096
#define CM 192
#define DI 384
#define DS 16
#define DTR 12
#define M_ROWS (BATCH * L)   // 16384
#define NCH 128
#define CHL (L / NCH)        // 32
#define BDN (BATCH * DI * DS) // 24576
#define NX (2 * DI)          // 768

// ---------------- scratch (device globals; no allocation) ----------------
__device__ float g_xi[(size_t)M_ROWS * DI];
__device__ float g_z[(size_t)M_ROWS * DI];
__device__ float g_u[(size_t)M_ROWS * DI];
__device__ float g_delta[(size_t)M_ROWS * DI];
__device__ float g_dtr[(size_t)M_ROWS * DTR];
__device__ float g_Bs[(size_t)M_ROWS * DS];
__device__ float g_Cs[(size_t)M_ROWS * DS];
__device__ float g_y[(size_t)M_ROWS * DI];
__device__ float g_hpart[(size_t)NCH * BDN];
__device__ float g_aP[(size_t)NCH * BDN];
__device__ float g_hin[(size_t)NCH * BDN];
__device__ __nv_bfloat16 g_whi[(size_t)NX * CM];   // transposed: [n][k]
__device__ __nv_bfloat16 g_wlo[(size_t)NX * CM];

// ---------------- k_split_w: fp32 -> bf16 hi/lo (weights only) ----------------
__global__ void k_split_w(const float* __restrict__ Win)
{
    const int i = blockIdx.x * 256 + threadIdx.x;
    if (i >= CM * NX) return;
    const int k = i / NX, n = i % NX;
    const float v = Win[i];
    const __nv_bfloat16 h = __float2bfloat16(v);
    g_whi[(size_t)n * CM + k] = h;
    g_wlo[(size_t)n * CM + k] = __float2bfloat16(v - __bfloat162float(h));
}

// ---------------- K1: xz = x @ W_in via bf16x3 mma.sync + ldmatrix ----------------
#define KP 40   // bf16 row pitch (80B): conflict-free ldmatrix

__device__ __forceinline__ void mma_bf16(float* d, const uint32_t* a, const uint32_t* b)
{
    asm volatile(
        "mma.sync.aligned.m16n8k16.row.col.f32.bf16.bf16.f32 "
        "{%0,%1,%2,%3}, {%4,%5,%6,%7}, {%8,%9}, {%0,%1,%2,%3};"
        : "+f"(d[0]), "+f"(d[1]), "+f"(d[2]), "+f"(d[3])
        : "r"(a[0]), "r"(a[1]), "r"(a[2]), "r"(a[3]), "r"(b[0]), "r"(b[1]));
}
#define LDSM4(r0, r1, r2, r3, addr) \
    asm volatile("ldmatrix.sync.aligned.m8n8.x4.shared.b16 {%0,%1,%2,%3}, [%4];" \
                 : "=r"(r0), "=r"(r1), "=r"(r2), "=r"(r3) : "r"(addr))

__device__ __forceinline__ uint32_t sptr(const void* p)
{
    return (uint32_t)__cvta_generic_to_shared(p);
}

__global__ __launch_bounds__(256) void k_gemm_mma(const float* __restrict__ X)
{
    __shared__ __nv_bfloat16 sAh[128][KP], sAl[128][KP], sBh[128][KP], sBl[128][KP];
    const int tid = threadIdx.x;
    const int wid = tid >> 5, t = tid & 31;
    const int m0 = blockIdx.x * 128, n0 = blockIdx.y * 128;
    const int wr = wid & 3, wc = wid >> 2;
    const int g = t >> 2, c2 = (t & 3) * 2;
    // ldmatrix x4 per-lane row/col pattern (same for A and B)
    const int qrow = ((t >> 3) & 1) * 8 + (t & 7);
    const int qcol = (t >> 4) * 8;

    float acc[2][8][4];
#pragma unroll
    for (int mt = 0; mt < 2; mt++)
#pragma unroll
        for (int nt = 0; nt < 8; nt++)
#pragma unroll
            for (int e = 0; e < 4; e++) acc[mt][nt][e] = 0.f;

    const int lr = tid >> 1;            // load row 0..127
    const int lh = (tid & 1) * 16;      // 16-element half

    for (int kc = 0; kc < CM; kc += 32) {
        // --- A: load fp32 x, split hi/lo in regs, store bf16 to smem ---
        {
            const float* xp = X + (size_t)(m0 + lr) * CM + kc + lh;
            uint32_t hi[8], lo[8];
#pragma unroll
            for (int q = 0; q < 4; q++) {
                float4 v = *(const float4*)(xp + q * 4);
                __nv_bfloat16 h0 = __float2bfloat16(v.x), h1 = __float2bfloat16(v.y),
                              h2 = __float2bfloat16(v.z), h3 = __float2bfloat16(v.w);
                __nv_bfloat162 H0(h0, h1), H1(h2, h3);
                __nv_bfloat162 L0(__float2bfloat16(v.x - __bfloat162float(h0)),
                                  __float2bfloat16(v.y - __bfloat162float(h1)));
                __nv_bfloat162 L1(__float2bfloat16(v.z - __bfloat162float(h2)),
                                  __float2bfloat16(v.w - __bfloat162float(h3)));
                hi[q * 2] = *(uint32_t*)&H0; hi[q * 2 + 1] = *(uint32_t*)&H1;
                lo[q * 2] = *(uint32_t*)&L0; lo[q * 2 + 1] = *(uint32_t*)&L1;
            }
            *(uint4*)&sAh[lr][lh]     = make_uint4(hi[0], hi[1], hi[2], hi[3]);
            *(uint4*)&sAh[lr][lh + 8] = make_uint4(hi[4], hi[5], hi[6], hi[7]);
            *(uint4*)&sAl[lr][lh]     = make_uint4(lo[0], lo[1], lo[2], lo[3]);
            *(uint4*)&sAl[lr][lh + 8] = make_uint4(lo[4], lo[5], lo[6], lo[7]);
            // --- B: pre-split bf16 weights ---
            const __nv_bfloat16* bh = g_whi + (size_t)(n0 + lr) * CM + kc + lh;
            const __nv_bfloat16* bl = g_wlo + (size_t)(n0 + lr) * CM + kc + lh;
            *(uint4*)&sBh[lr][lh]     = *(const uint4*)(bh);
            *(uint4*)&sBh[lr][lh + 8] = *(const uint4*)(bh + 8);
            *(uint4*)&sBl[lr][lh]     = *(const uint4*)(bl);
            *(uint4*)&sBl[lr][lh + 8] = *(const uint4*)(bl + 8);
        }
        __syncthreads();

#pragma unroll
        for (int ks = 0; ks < 2; ks++) {
            const int K0 = ks * 16;
            uint32_t ahf[2][4], alf[2][4];
#pragma unroll
            for (int mt = 0; mt < 2; mt++) {
                const int R = wr * 32 + mt * 16 + qrow;
                LDSM4(ahf[mt][0], ahf[mt][1], ahf[mt][2], ahf[mt][3],
                      sptr(&sAh[R][K0 + qcol]));
                LDSM4(alf[mt][0], alf[mt][1], alf[mt][2], alf[mt][3],
                      sptr(&sAl[R][K0 + qcol]));
            }
#pragma unroll
            for (int ntp = 0; ntp < 4; ntp++) {
                const int N = wc * 64 + ntp * 16 + qrow;
                uint32_t h0, h1, h2, h3, l0, l1, l2, l3;
                LDSM4(h0, h1, h2, h3, sptr(&sBh[N][K0 + qcol]));
                LDSM4(l0, l1, l2, l3, sptr(&sBl[N][K0 + qcol]));
                uint32_t bhf0[2] = {h0, h2}, bhf1[2] = {h1, h3};
                uint32_t blf0[2] = {l0, l2}, blf1[2] = {l1, l3};
#pragma unroll
                for (int mt = 0; mt < 2; mt++) {
                    mma_bf16(acc[mt][ntp * 2],     ahf[mt], bhf0);
                    mma_bf16(acc[mt][ntp * 2],     ahf[mt], blf0);
                    mma_bf16(acc[mt][ntp * 2],     alf[mt], bhf0);
                    mma_bf16(acc[mt][ntp * 2 + 1], ahf[mt], bhf1);
                    mma_bf16(acc[mt][ntp * 2 + 1], ahf[mt], blf1);
                    mma_bf16(acc[mt][ntp * 2 + 1], alf[mt], bhf1);
                }
            }
        }
        __syncthreads();
    }

    // epilogue: direct float2 stores
    const bool toZ = (n0 >= DI);
#pragma unroll
    for (int mt = 0; mt < 2; mt++) {
#pragma unroll
        for (int nt = 0; nt < 8; nt++) {
            int nc = n0 + wc * 64 + nt * 8 + c2;
            if (toZ) nc -= DI;
            const int r0 = m0 + wr * 32 + mt * 16 + g;
            float* base = toZ ? g_z : g_xi;
            *(float2*)&base[(size_t)r0 * DI + nc] =
                make_float2(acc[mt][nt][0], acc[mt][nt][1]);
            *(float2*)&base[(size_t)(r0 + 8) * DI + nc] =
                make_float2(acc[mt][nt][2], acc[mt][nt][3]);
        }
    }
}

// ---------------- conv: depthwise 3x3 + bias + SiLU, 8 outputs/thread ----------------
// block (128 d, 8 h-rows); tile = 8h x 8w outputs, 10x10 halo in dynamic smem.
__global__ __launch_bounds__(1024) void k_conv(const float* __restrict__ cw,
                                               const float* __restrict__ cb)
{
    extern __shared__ float cs[];   // [100][128]
    const int b = blockIdx.z;
    const int d = blockIdx.y * 128 + threadIdx.x;
    const int h0 = (blockIdx.x >> 3) * 8;
    const int w0 = (blockIdx.x & 7) * 8;
    const int tx = threadIdx.x, ty = threadIdx.y;
    const size_t base = (size_t)b * L * DI;

#pragma unroll
    for (int i = 0; i < 13; i++) {
        const int p = ty + 8 * i;
        if (p < 100) {
            const int rr = p / 10, cc = p % 10;
            const int hh = h0 + rr - 1, ww = w0 + cc - 1;
            float v = 0.f;
            if (hh >= 0 && hh < 64 && ww >= 0 && ww < 64)
                v = g_xi[base + (size_t)(hh * 64 + ww) * DI + d];
            cs[p * 128 + tx] = v;
        }
    }
    __syncthreads();

    float W[9];
#pragma unroll
    for (int i = 0; i < 9; i++) W[i] = cw[d * 9 + i];
    const float bias = cb[d];

    float acc[8];
#pragma unroll
    for (int j = 0; j < 8; j++) acc[j] = bias;

#pragma unroll
    for (int r = 0; r < 3; r++) {
        float rv[10];
#pragma unroll
        for (int c = 0; c < 10; c++) rv[c] = cs[((ty + r) * 10 + c) * 128 + tx];
#pragma unroll
        for (int j = 0; j < 8; j++) {
            acc[j] = fmaf(rv[j],     W[r * 3 + 0], acc[j]);
            acc[j] = fmaf(rv[j + 1], W[r * 3 + 1], acc[j]);
            acc[j] = fmaf(rv[j + 2], W[r * 3 + 2], acc[j]);
        }
    }
#pragma unroll
    for (int j = 0; j < 8; j++) {
        const float sig = 1.f / (1.f + __expf(-acc[j]));
        g_u[base + (size_t)((h0 + ty) * 64 + w0 + j) * DI + d] = acc[j] * sig;
    }
}

// ---------------- k_xdbl: x_dbl = u @ Wx  (16384 x 44, K=384) ----------------
__global__ __launch_bounds__(256) void k_xdbl(const float* __restrict__ Wx)
{
    __shared__ float Us[16][64];
    __shared__ float Wxs[16][48];
    const int tid = threadIdx.x;
    const int m0 = blockIdx.x * 64;
    const int tm = tid / 16, tn = tid % 16;

    float acc[4][3];
#pragma unroll
    for (int i = 0; i < 4; i++)
#pragma unroll
        for (int j = 0; j < 3; j++) acc[i][j] = 0.f;

    const int urow = tid / 4, ukq = (tid % 4) * 4;

    for (int k0 = 0; k0 < DI; k0 += 16) {
        float4 uv = *(const float4*)&g_u[(size_t)(m0 + urow) * DI + k0 + ukq];
        Us[ukq + 0][urow] = uv.x;
        Us[ukq + 1][urow] = uv.y;
        Us[ukq + 2][urow] = uv.z;
        Us[ukq + 3][urow] = uv.w;
#pragma unroll
        for (int i = 0; i < 3; i++) {
            const int f = tid + i * 256;
            const int rr = f / 48, c = f % 48;
            Wxs[rr][c] = (c < 44) ? Wx[(size_t)(k0 + rr) * 44 + c] : 0.f;
        }
        __syncthreads();
#pragma unroll
        for (int k = 0; k < 16; k++) {
            float4 a4 = *(const float4*)&Us[k][tm * 4];
            float a[4] = {a4.x, a4.y, a4.z, a4.w};
            float b0 = Wxs[k][tn * 3 + 0];
            float b1 = Wxs[k][tn * 3 + 1];
            float b2 = Wxs[k][tn * 3 + 2];
#pragma unroll
            for (int i = 0; i < 4; i++) {
                acc[i][0] = fmaf(a[i], b0, acc[i][0]);
                acc[i][1] = fmaf(a[i], b1, acc[i][1]);
                acc[i][2] = fmaf(a[i], b2, acc[i][2]);
            }
        }
        __syncthreads();
    }
#pragma unroll
    for (int i = 0; i < 4; i++) {
        const size_t m = (size_t)(m0 + tm * 4 + i);
#pragma unroll
        for (int j = 0; j < 3; j++) {
            const int c = tn * 3 + j;
            const float v = acc[i][j];
            if (c < DTR)            g_dtr[m * DTR + c] = v;
            else if (c < DTR + DS)  g_Bs[m * DS + (c - DTR)] = v;
            else if (c < 44)        g_Cs[m * DS + (c - DTR - DS)] = v;
        }
    }
}

// ---------------- k_promptC: Cs += prompt @ Wp (16384 x 16, K=192) ----------------
__global__ void k_promptC(const float* __restrict__ prompt, const float* __restrict__ Wp)
{
    __shared__ float p[16 * 192];
    const int tid = threadIdx.x;
    const int row0 = blockIdx.x * 16;
    const float4* src = (const float4*)(prompt + (size_t)row0 * CM);
#pragma unroll
    for (int i = 0; i < 3; i++)
        ((float4*)p)[tid + i * 256] = src[tid + i * 256];
    __syncthreads();

    const int r = tid / 16, n = tid % 16;
    float a0 = 0.f, a1 = 0.f;
    const float* pr = p + r * CM;
#pragma unroll 8
    for (int k = 0; k < CM; k += 2) {
        a0 = fmaf(pr[k],     Wp[(size_t)k * DS + n],       a0);
        a1 = fmaf(pr[k + 1], Wp[(size_t)(k + 1) * DS + n], a1);
    }
    g_Cs[(size_t)(row0 + r) * DS + n] += a0 + a1;
}

// ---------------- k_delta ----------------
__global__ void k_delta(const float* __restrict__ Wdt, const float* __restrict__ bdt)
{
    __shared__ float sd[8][DTR];
    const int tid = threadIdx.x; // 384
    const int row0 = blockIdx.x * 8;
    if (tid < 8 * DTR) sd[tid / DTR][tid % DTR] = g_dtr[(size_t)(row0 + tid / DTR) * DTR + tid % DTR];
    __syncthreads();

    float w[DTR];
#pragma unroll
    for (int rr = 0; rr < DTR; rr++) w[rr] = Wdt[(size_t)rr * DI + tid];
    const float bb = bdt[tid];
#pragma unroll
    for (int rr = 0; rr < 8; rr++) {
        float acc = bb;
#pragma unroll
        for (int r2 = 0; r2 < DTR; r2++) acc = fmaf(sd[rr][r2], w[r2], acc);
        const float sp = acc > 20.f ? acc : log1pf(__expf(acc));
        g_delta[(size_t)(row0 + rr) * DI + tid] = sp;
    }
}

// ---------------- scan helpers ----------------
__device__ __forceinline__ void pow_chain(float e1, float* av)
{
    const float e2 = e1 * e1, e4 = e2 * e2, e8 = e4 * e4;
    av[0] = e1;       av[1] = e2;       av[2] = e2 * e1;   av[3] = e4;
    av[4] = e4 * e1;  av[5] = e4 * e2;  av[6] = e4 * av[2]; av[7] = e8;
    av[8] = e8 * e1;  av[9] = e8 * e2;  av[10] = e8 * av[2]; av[11] = e8 * e4;
    av[12] = e8 * av[4]; av[13] = e8 * av[5]; av[14] = e8 * av[6]; av[15] = e8 * e8;
}

__device__ __forceinline__ bool a_structured(const float* __restrict__ Alog, int d, float& A0)
{
    A0 = -__expf(Alog[(size_t)d * DS]);
    bool ok = true;
#pragma unroll
    for (int n = 1; n < DS; n++) {
        const float Av = -__expf(Alog[(size_t)d * DS + n]);
        ok &= fabsf(Av - (n + 1) * A0) <= 1e-4f * fabsf((n + 1) * A0);
    }
    return ok;
}

// ---------------- S1 ----------------
__global__ void k_scan1(const float* __restrict__ Alog)
{
    __shared__ float sB[CHL][DS];
    const int d = blockIdx.x * 128 + threadIdx.x;
    const int c = blockIdx.y;
    const int b = blockIdx.z;
    const int l0 = c * CHL;

    {
        const float4* src = (const float4*)g_Bs + ((size_t)b * L + l0) * 4;
        ((float4*)sB)[threadIdx.x] = src[threadIdx.x];
    }

    float A0;
    const bool st = a_structured(Alog, d, A0);
    __syncthreads();

    float h[DS];
#pragma unroll
    for (int n = 0; n < DS; n++) h[n] = 0.f;
    float dsum = 0.f;

    const float* dp = g_delta + ((size_t)b * L + l0) * DI + d;
    const float* up = g_u + ((size_t)b * L + l0) * DI + d;

    if (st) {
        for (int l = 0; l < CHL; l++) {
            const float dl = dp[(size_t)l * DI];
            const float du = dl * up[(size_t)l * DI];
            dsum += dl;
            float av[DS];
            pow_chain(__expf(dl * A0), av);
#pragma unroll
            for (int n = 0; n < DS; n++) h[n] = fmaf(av[n], h[n], du * sB[l][n]);
        }
        float av[DS];
        pow_chain(__expf(dsum * A0), av);
        const size_t base = (size_t)c * BDN + ((size_t)b * DI + d) * DS;
#pragma unroll
        for (int n = 0; n < DS; n++) {
            g_hpart[base + n] = h[n];
            g_aP[base + n] = av[n];
        }
    } else {
        float A[DS];
#pragma unroll
        for (int n = 0; n < DS; n++) A[n] = -__expf(Alog[(size_t)d * DS + n]);
        for (int l = 0; l < CHL; l++) {
            const float dl = dp[(size_t)l * DI];
            const float du = dl * up[(size_t)l * DI];
            dsum += dl;
#pragma unroll
            for (int n = 0; n < DS; n++)
                h[n] = fmaf(__expf(dl * A[n]), h[n], du * sB[l][n]);
        }
        const size_t base = (size_t)c * BDN + ((size_t)b * DI + d) * DS;
#pragma unroll
        for (int n = 0; n < DS; n++) {
            g_hpart[base + n] = h[n];
            g_aP[base + n] = __expf(A[n] * dsum);
        }
    }
}

// ---------------- S2 ----------------
__global__ void k_scan2()
{
    const int idx = blockIdx.x * 256 + threadIdx.x;
    if (idx >= BDN) return;
    float h = 0.f;
    for (int c = 0; c < NCH; c++) {
        const size_t o = (size_t)c * BDN + idx;
        g_hin[o] = h;
        h = fmaf(g_aP[o], h, g_hpart[o]);
    }
}

// ---------------- S3 ----------------
__global__ void k_scan3(const float* __restrict__ Alog, const float* __restrict__ Dvec)
{
    __shared__ float sB[CHL][DS];
    __shared__ float sC[CHL][DS];
    const int d = blockIdx.x * 128 + threadIdx.x;
    const int c = blockIdx.y;
    const int b = blockIdx.z;
    const int l0 = c * CHL;

    {
        const float4* srcB = (const float4*)g_Bs + ((size_t)b * L + l0) * 4;
        const float4* srcC = (const float4*)g_Cs + ((size_t)b * L + l0) * 4;
        ((float4*)sB)[threadIdx.x] = srcB[threadIdx.x];
        ((float4*)sC)[threadIdx.x] = srcC[threadIdx.x];
    }

    float A0;
    const bool st = a_structured(Alog, d, A0);
    const float Dd = Dvec[d];
    __syncthreads();

    float h[DS];
    {
        const size_t base = (size_t)c * BDN + ((size_t)b * DI + d) * DS;
#pragma unroll
        for (int n = 0; n < DS; n++) h[n] = g_hin[base + n];
    }

    const float* dp = g_delta + ((size_t)b * L + l0) * DI + d;
    const float* up = g_u + ((size_t)b * L + l0) * DI + d;
    float* yp = g_y + ((size_t)b * L + l0) * DI + d;

    if (st) {
        for (int l = 0; l < CHL; l++) {
            const float dl = dp[(size_t)l * DI];
            const float uu = up[(size_t)l * DI];
            const float du = dl * uu;
            float av[DS];
            pow_chain(__expf(dl * A0), av);
            float y = uu * Dd;
#pragma unroll
            for (int n = 0; n < DS; n++) {
                h[n] = fmaf(av[n], h[n], du * sB[l][n]);
                y = fmaf(h[n], sC[l][n], y);
            }
            yp[(size_t)l * DI] = y;
        }
    } else {
        float A[DS];
#pragma unroll
        for (int n = 0; n < DS; n++) A[n] = -__expf(Alog[(size_t)d * DS + n]);
        for (int l = 0; l < CHL; l++) {
            const float dl = dp[(size_t)l * DI];
            const float uu = up[(size_t)l * DI];
            const float du = dl * uu;
            float y = uu * Dd;
#pragma unroll
            for (int n = 0; n < DS; n++) {
                h[n] = fmaf(__expf(dl * A[n]), h[n], du * sB[l][n]);
                y = fmaf(h[n], sC[l][n], y);
            }
            yp[(size_t)l * DI] = y;
        }
    }
}

// ---------------- K4: LayerNorm + SiLU gate + out GEMM ----------------
__global__ void k_out(const float* __restrict__ lng, const float* __restrict__ lnb,
                      const float* __restrict__ Wout, float* __restrict__ out)
{
    __shared__ float yg[16][DI];
    __shared__ float Wt[16][CM];
    const int tid = threadIdx.x; // 256
    const int r0 = blockIdx.x * 16;
    const int warp = tid >> 5, lane = tid & 31;

#pragma unroll
    for (int rr = 0; rr < 2; rr++) {
        const int r = warp * 2 + rr;
        const size_t row = (size_t)(r0 + r);
        float v[12];
        float s = 0.f, sq = 0.f;
#pragma unroll
        for (int i = 0; i < 12; i++) {
            v[i] = g_y[row * DI + lane + 32 * i];
            s += v[i];
            sq = fmaf(v[i], v[i], sq);
        }
#pragma unroll
        for (int o = 16; o > 0; o >>= 1) {
            s += __shfl_xor_sync(0xFFFFFFFFu, s, o);
            sq += __shfl_xor_sync(0xFFFFFFFFu, sq, o);
        }
        const float mu = s * (1.f / DI);
        const float var = sq * (1.f / DI) - mu * mu;
        const float rs = rsqrtf(var + 1e-5f);
#pragma unroll
        for (int i = 0; i < 12; i++) {
            const int k = lane + 32 * i;
            const float zn = g_z[row * DI + k];
            const float sig = 1.f / (1.f + __expf(-zn));
            const float g = fmaf((v[i] - mu) * rs, lng[k], lnb[k]);
            yg[r][k] = g * zn * sig;
        }
    }
    __syncthreads();

    const int tr = tid >> 6;
    const int tc = tid & 63;
    float acc[4][3];
#pragma unroll
    for (int r = 0; r < 4; r++)
#pragma unroll
        for (int cc = 0; cc < 3; cc++) acc[r][cc] = 0.f;

    for (int kt = 0; kt < DI; kt += 16) {
#pragma unroll
        for (int i = 0; i < 3; i++) {
            const int e = tid + i * 256;
            const int kr = e / 48;
            const int c4 = (e % 48) * 4;
            *(float4*)&Wt[kr][c4] = *(const float4*)&Wout[(size_t)(kt + kr) * CM + c4];
        }
        __syncthreads();
#pragma unroll
        for (int k = 0; k < 16; k++) {
            const float w0 = Wt[k][tc * 3 + 0];
            const float w1 = Wt[k][tc * 3 + 1];
            const float w2 = Wt[k][tc * 3 + 2];
#pragma unroll
            for (int r = 0; r < 4; r++) {
                const float a = yg[tr * 4 + r][kt + k];
                acc[r][0] = fmaf(a, w0, acc[r][0]);
                acc[r][1] = fmaf(a, w1, acc[r][1]);
                acc[r][2] = fmaf(a, w2, acc[r][2]);
            }
        }
        __syncthreads();
    }
#pragma unroll
    for (int r = 0; r < 4; r++) {
        const size_t row = (size_t)(r0 + tr * 4 + r);
#pragma unroll
        for (int cc = 0; cc < 3; cc++)
            out[row * CM + tc * 3 + cc] = acc[r][cc];
    }
}

// ---------------- launch ----------------
extern "C" void kernel_launch(void* const* d_in, const int* in_sizes, int n_in,
                              void* d_out, int out_size)
{
    const float* x      = (const float*)d_in[0];
    const float* prompt = (const float*)d_in[1];
    const float* W_in   = (const float*)d_in[2];
    const float* conv_w = (const float*)d_in[3];
    const float* conv_b = (const float*)d_in[4];
    const float* Wx     = (const float*)d_in[5];
    const float* Wdt    = (const float*)d_in[6];
    const float* b_dt   = (const float*)d_in[7];
    const float* A_log  = (const float*)d_in[8];
    const float* Dv     = (const float*)d_in[9];
    const float* Wp     = (const float*)d_in[10];
    const float* ln_g   = (const float*)d_in[11];
    const float* ln_b   = (const float*)d_in[12];
    const float* Wout   = (const float*)d_in[13];
    float* out = (float*)d_out;

    static bool attr_set = false;
    if (!attr_set) {
        cudaFuncSetAttribute(k_conv, cudaFuncAttributeMaxDynamicSharedMemorySize, 51200);
        attr_set = true;
    }

    k_split_w<<<(CM * NX + 255) / 256, 256>>>(W_in);
    k_gemm_mma<<<dim3(M_ROWS / 128, NX / 128), 256>>>(x);
    k_conv<<<dim3(64, 3, BATCH), dim3(128, 8), 51200>>>(conv_w, conv_b);
    k_xdbl<<<M_ROWS / 64, 256>>>(Wx);
    k_promptC<<<M_ROWS / 16, 256>>>(prompt, Wp);
    k_delta<<<M_ROWS / 8, DI>>>(Wdt, b_dt);
    k_scan1<<<dim3(DI / 128, NCH, BATCH), 128>>>(A_log);
    k_scan2<<<(BDN + 255) / 256, 256>>>();
    k_scan3<<<dim3(DI / 128, NCH, BATCH), 128>>>(A_log, Dv);
    k_out<<<M_ROWS / 16, 256>>>(ln_g, ln_b, Wout, out);
}